// round 11
// baseline (speedup 1.0000x reference)
#include <cuda_runtime.h>
#include <math.h>

#define NK 10
#define NIMG 8      // 0..2 = A channels, 3..7 = packed kernel pairs
#define GRID 512
#define NTHR 256

// ---------------- scratch (static device globals; no allocation) ----------------
__device__ __align__(16) float2 g_cA[NIMG * 65536];
__device__ __align__(16) float2 g_cB[NIMG * 65536];
__device__ float2 g_tw[128];            // tw[Ns+k] = exp(-i*pi*k/(2*Ns)), Ns in {1,4,16,64}
__device__ float  g_Asum[256][256];
__device__ double g_part[NK][256];
__device__ double g_ksum[NK];
__device__ __align__(16) float g_U3[3][256][256];
__device__ __align__(16) float g_mu[256*256*6];

// software grid barrier state (generation-based; self-resetting)
__device__ unsigned g_count = 0;
__device__ volatile unsigned g_gen = 0;

__constant__ int c_grp[NK]   = {0,0,0,1,1,1,2,2,2,0};
__constant__ int c_pairA[5]  = {0,0,1,2,2};   // C0[2j]
__constant__ int c_pairB[5]  = {0,1,1,2,0};   // C0[2j+1]

__device__ __forceinline__ float2 cadd(float2 a, float2 b){ return make_float2(a.x+b.x, a.y+b.y); }
__device__ __forceinline__ float2 csub(float2 a, float2 b){ return make_float2(a.x-b.x, a.y-b.y); }
__device__ __forceinline__ float2 cmul(float2 a, float2 b){
    return make_float2(a.x*b.x - a.y*b.y, a.x*b.y + a.y*b.x);
}

// ---------------- grid-wide barrier (all GRID blocks co-resident) ----------------
__device__ __forceinline__ void gsync() {
    __syncthreads();
    if (threadIdx.x == 0) {
        __threadfence();
        unsigned gen = g_gen;
        if (atomicAdd(&g_count, 1u) == GRID - 1) {
            g_count = 0;
            __threadfence();
            g_gen = gen + 1;
        } else {
            while (g_gen == gen) { __nanosleep(64); }
            __threadfence();
        }
    }
    __syncthreads();
}

// ---------------- radix-4 Stockham 256-pt FFT row-quad job ----------------
// mode 0: g_cA -> g_cB ; mode 1: g_cB -> g_cA ; mode 2: fused mult+conj, g_cA spectra -> g_cB
__device__ __forceinline__ void fft_job(int mode, int img, int rb, int tid,
                                        float2 (*sb)[4][258]) {
    int tx = tid & 63;
    int ty = tid >> 6;
    int row = rb + ty;
    float2* B0 = sb[0][ty];

    if (mode == 2) {
        // conj(Q), Q = fK_a*fA_a + i*fK_b*fA_b ; fK_a = Re(Kpack), fK_b = Im(Kpack)
        const float2* Kp = g_cA + (3+img)*65536 + row*256;
        const float2* Fa = g_cA + c_pairA[img]*65536 + row*256;
        const float2* Fb = g_cA + c_pairB[img]*65536 + row*256;
        #pragma unroll
        for (int i = 0; i < 4; i++) {
            int q = tx + i*64;
            float2 kp = Kp[q];
            float2 fa = Fa[q];
            float2 fb = Fb[q];
            B0[q] = make_float2(kp.x*fa.x - kp.y*fb.y, -(kp.x*fa.y) - kp.y*fb.x);
        }
    } else {
        const float2* src = (mode == 0 ? g_cA : g_cB) + img*65536 + row*256;
        #pragma unroll
        for (int i = 0; i < 4; i++) B0[tx + i*64] = src[tx + i*64];
    }
    __syncthreads();

    #pragma unroll
    for (int p = 0; p < 4; p++) {
        float2* X = sb[p & 1][ty];
        float2* Y = sb[(p + 1) & 1][ty];
        int Ns = 1 << (2*p);
        int kk = tx & (Ns - 1);
        float2 av = X[tx];
        float2 bv = X[tx + 64];
        float2 cv = X[tx + 128];
        float2 dv = X[tx + 192];
        if (p > 0) {                       // stage 0 twiddles are all 1
            float2 w1 = g_tw[Ns + kk];
            float2 w2 = cmul(w1, w1);
            float2 w3 = cmul(w2, w1);
            bv = cmul(bv, w1); cv = cmul(cv, w2); dv = cmul(dv, w3);
        }
        float2 t0 = cadd(av, cv), t1 = csub(av, cv), t2 = cadd(bv, dv);
        float2 bd = csub(bv, dv);
        float2 t3 = make_float2(bd.y, -bd.x);      // -i*(b-d)
        int o = ((tx >> (2*p)) << (2*p + 2)) + kk;
        Y[o]        = cadd(t0, t2);
        Y[o + Ns]   = cadd(t1, t3);
        Y[o + 2*Ns] = csub(t0, t2);
        Y[o + 3*Ns] = csub(t1, t3);
        __syncthreads();
    }

    float2* dst = (mode == 1 ? g_cA : g_cB) + img*65536;
    #pragma unroll
    for (int i = 0; i < 4; i++) {
        int e = tid + i*256;
        int q = e >> 2, rr = e & 3;
        dst[q*256 + rb + rr] = sb[0][rr][q];
    }
}

// ---------------- kernel-profile value ----------------
__device__ __forceinline__ float kval(float D, float invS,
                                      const float* a, const float* b, const float* w, int k) {
    float Dk = D * invS;
    float val = 0.0f;
    if (Dk < 2.9f) {   // reference's fp32 tanh saturates -> sig exactly 0 past ~2.58
        float ker = 0.0f;
        #pragma unroll
        for (int t = 0; t < 3; t++) {
            float d = Dk - a[k*3+t];
            ker += b[k*3+t] * __expf(-__fdividef(d*d, w[k*3+t]));
        }
        // 0.5*(tanh(-(Dk-1)*5)+1) == 1/(1+exp((Dk-1)*10))
        float sig = __fdividef(1.0f, 1.0f + __expf((Dk - 1.0f) * 10.0f));
        val = sig * ker;
    }
    return val;
}

__device__ __forceinline__ float padv(const float* p, int xx, int yy) {
    return (xx >= 0 && xx < 256 && yy >= 0 && yy < 256) ? p[xx*256 + yy] : 0.0f;
}

// ---------------- the single persistent megakernel ----------------
__global__ void __launch_bounds__(NTHR, 4) mega_kernel(
    const float* __restrict__ A,
    const float* __restrict__ R,
    const float* __restrict__ r,
    const float* __restrict__ m,
    const float* __restrict__ s,
    const float* __restrict__ h,
    const float* __restrict__ a,
    const float* __restrict__ b,
    const float* __restrict__ w,
    float* __restrict__ out)
{
    __shared__ __align__(16) unsigned char smraw[16848];
    float2 (*sb)[4][258] = (float2 (*)[4][258])smraw;     // 16512 B (FFT ping-pong)
    double* sd  = (double*)smraw;                          // 2048 B (reductions)
    float*  s_mu = (float*)smraw;                          // 11232 B (gather)
    float*  s_a  = (float*)(smraw + 468*6*4);              // 5616 B

    int tid = threadIdx.x;
    int blk = blockIdx.x;

    // ---------- P0: prep + kbuild (1536 jobs, 3 per block) ----------
    for (int t = 0; t < 3; t++) {
        int job = blk + GRID * t;
        int p = job >> 8;          // 0..4 = kernel pair, 5 = prep
        int i = job & 255;
        if (p == 5) {
            int x = i, y = tid;
            float a0 = A[(x*256+y)*3+0];
            float a1 = A[(x*256+y)*3+1];
            float a2 = A[(x*256+y)*3+2];
            g_Asum[x][y] = a0 + a1 + a2;
            int idx = x*256 + y;
            g_cA[0*65536 + idx] = make_float2(a0, 0.f);
            g_cA[1*65536 + idx] = make_float2(a1, 0.f);
            g_cA[2*65536 + idx] = make_float2(a2, 0.f);
            if (x == 0 && y < 128) {
                if (y == 0) {
                    g_tw[0] = make_float2(1.f, 0.f);
                } else {
                    int pp = 31 - __clz(y);
                    int Ns = 1 << pp;
                    int kk = y - Ns;
                    double ang = -M_PI * (double)kk / (2.0 * (double)Ns);
                    g_tw[y] = make_float2((float)cos(ang), (float)sin(ang));
                }
            }
        } else {
            int j = tid;
            int k0 = 2*p, k1 = 2*p + 1;
            float fdx = (i < 128) ? (float)i : (float)(i - 256);
            float fdy = (j < 128) ? (float)j : (float)(j - 256);
            float D = sqrtf(fdx*fdx + fdy*fdy);
            float Rv = R[0] + 15.0f;
            float v0 = kval(D, __fdividef(1.0f, Rv * r[k0]), a, b, w, k0);
            float v1 = kval(D, __fdividef(1.0f, Rv * r[k1]), a, b, w, k1);
            g_cA[(3+p)*65536 + i*256 + j] = make_float2(v0, v1);

            sd[j] = (double)v0;
            __syncthreads();
            for (int st = 128; st > 0; st >>= 1) {
                if (j < st) sd[j] += sd[j + st];
                __syncthreads();
            }
            if (j == 0) g_part[k0][i] = sd[0];
            __syncthreads();
            sd[j] = (double)v1;
            __syncthreads();
            for (int st = 128; st > 0; st >>= 1) {
                if (j < st) sd[j] += sd[j + st];
                __syncthreads();
            }
            if (j == 0) g_part[k1][i] = sd[0];
        }
        __syncthreads();
    }
    gsync();

    // ---------- P1: forward FFT pass 1 (8 images, 512 jobs) ----------
    fft_job(0, blk >> 6, (blk & 63) * 4, tid, sb);
    gsync();

    // ---------- P2: forward FFT pass 2 ----------
    fft_job(1, blk >> 6, (blk & 63) * 4, tid, sb);
    gsync();

    // ---------- P3: inverse pass 1 (fused mult+conj, 5 imgs, 320 jobs) + ksum ----------
    if (blk < 320) {
        fft_job(2, blk >> 6, (blk & 63) * 4, tid, sb);
    } else if (blk == 400) {
        int j = tid;
        for (int k = 0; k < NK; k++) {
            sd[j] = g_part[k][j];
            __syncthreads();
            for (int st = 128; st > 0; st >>= 1) {
                if (j < st) sd[j] += sd[j + st];
                __syncthreads();
            }
            if (j == 0) g_ksum[k] = sd[0];
            __syncthreads();
        }
    }
    gsync();

    // ---------- P4: inverse pass 2 (5 imgs, 320 jobs) ----------
    if (blk < 320) {
        fft_job(1, blk >> 6, (blk & 63) * 4, tid, sb);
    }
    gsync();

    // ---------- P5: growth + channel-group sums (all 512 blocks, 128 px each) ----------
    if (tid < 128) {
        int idx = blk * 128 + tid;
        int x = idx >> 8, y = idx & 255;
        float u0 = 0.f, u1 = 0.f, u2 = 0.f;
        #pragma unroll
        for (int j = 0; j < 5; j++) {
            float2 z = g_cA[j*65536 + idx];
            #pragma unroll
            for (int q = 0; q < 2; q++) {
                int k = 2*j + q;
                float inv = (float)(1.0 / (65536.0 * g_ksum[k]));
                float U = (q == 0 ? z.x : -z.y) * inv;
                float gg = (U - m[k]) / s[k];
                float gr = (__expf(-0.5f * gg * gg) * 2.0f - 1.0f) * h[k];
                int grp = c_grp[k];
                if (grp == 0) u0 += gr;
                else if (grp == 1) u1 += gr;
                else u2 += gr;
            }
        }
        g_U3[0][x][y] = u0;
        g_U3[1][x][y] = u1;
        g_U3[2][x][y] = u2;
    }
    gsync();

    // ---------- P6: sobel + flow F + mu (all 512 blocks, 128 px each) ----------
    if (tid < 128) {
        int idx = blk * 128 + tid;
        int x = idx >> 8, y = idx & 255;
        const float* As = &g_Asum[0][0];
        float nA0 = (padv(As,x-1,y-1) + 2.0f*padv(As,x-1,y) + padv(As,x-1,y+1))
                  - (padv(As,x+1,y-1) + 2.0f*padv(As,x+1,y) + padv(As,x+1,y+1));
        float nA1 = (padv(As,x-1,y-1) + 2.0f*padv(As,x,y-1) + padv(As,x+1,y-1))
                  - (padv(As,x-1,y+1) + 2.0f*padv(As,x,y+1) + padv(As,x+1,y+1));
        float px = (float)x + 0.5f;
        float py = (float)y + 0.5f;
        #pragma unroll
        for (int c = 0; c < 3; c++) {
            const float* Uc = &g_U3[c][0][0];
            float nU0 = (padv(Uc,x-1,y-1) + 2.0f*padv(Uc,x-1,y) + padv(Uc,x-1,y+1))
                      - (padv(Uc,x+1,y-1) + 2.0f*padv(Uc,x+1,y) + padv(Uc,x+1,y+1));
            float nU1 = (padv(Uc,x-1,y-1) + 2.0f*padv(Uc,x,y-1) + padv(Uc,x+1,y-1))
                      - (padv(Uc,x-1,y+1) + 2.0f*padv(Uc,x,y+1) + padv(Uc,x+1,y+1));
            float Ac = A[(x*256+y)*3 + c];
            float al = Ac * (1.0f/3.0f);
            al = al * al;
            al = fminf(al, 1.0f);
            float F0 = nU0 * (1.0f - al) - nA0 * al;
            float F1 = nU1 * (1.0f - al) - nA1 * al;
            float d0 = fminf(fmaxf(0.2f * F0, -4.35f), 4.35f);
            float d1 = fminf(fmaxf(0.2f * F1, -4.35f), 4.35f);
            float mux = fminf(fmaxf(px + d0, 0.65f), 255.35f);
            float muy = fminf(fmaxf(py + d1, 0.65f), 255.35f);
            g_mu[idx*6 + c*2 + 0] = mux;
            g_mu[idx*6 + c*2 + 1] = muy;
        }
    }
    gsync();

    // ---------- P7: reintegration gather (512 tiles of 16x8) ----------
    {
        int bx = blk >> 5;            // 0..15  -> X0
        int by = blk & 31;            // 0..31  -> Y0
        int X0 = bx * 16, Y0 = by * 8;

        for (int idx = tid; idx < 26*18; idx += NTHR) {
            int ii = idx / 18, jj = idx - ii*18;
            int gi = (X0 - 5 + ii) & 255;
            int gj = (Y0 - 5 + jj) & 255;
            const float2* mu = (const float2*)(g_mu + (gi*256 + gj)*6);
            float2* d = (float2*)(s_mu + idx*6);
            d[0] = mu[0]; d[1] = mu[1]; d[2] = mu[2];
            s_a[idx*3+0] = A[(gi*256+gj)*3+0];
            s_a[idx*3+1] = A[(gi*256+gj)*3+1];
            s_a[idx*3+2] = A[(gi*256+gj)*3+2];
        }
        __syncthreads();

        if (tid < 128) {
            int ty = tid >> 3;        // 0..15 (x within tile)
            int tx = tid & 7;         // 0..7  (y within tile)
            int x = X0 + ty, y = Y0 + tx;
            float px = (float)x + 0.5f;
            float py = (float)y + 0.5f;
            float acc0 = 0.0f, acc1 = 0.0f, acc2 = 0.0f;
            const float inv = 1.0f / 1.69f;   // 1/(4*sigma^2)

            #pragma unroll
            for (int dx = -5; dx <= 5; ++dx) {
                int si = ty + 5 - dx;
                #pragma unroll
                for (int dy = -5; dy <= 5; ++dy) {
                    int sj = tx + 5 - dy;
                    int base = si*18 + sj;
                    const float* mu = s_mu + base*6;
                    const float* av = s_a + base*3;
                    #pragma unroll
                    for (int c = 0; c < 3; c++) {
                        float ax = 1.15f - fabsf(px - mu[2*c + 0]);
                        float ay = 1.15f - fabsf(py - mu[2*c + 1]);
                        ax = fminf(fmaxf(ax, 0.0f), 1.0f);
                        ay = fminf(fmaxf(ay, 0.0f), 1.0f);
                        float area = ax * ay * inv;
                        if (c == 0) acc0 = fmaf(av[0], area, acc0);
                        else if (c == 1) acc1 = fmaf(av[1], area, acc1);
                        else acc2 = fmaf(av[2], area, acc2);
                    }
                }
            }
            out[(x*256+y)*3 + 0] = acc0;
            out[(x*256+y)*3 + 1] = acc1;
            out[(x*256+y)*3 + 2] = acc2;
        }
    }
}

// ---------------- launch ----------------
extern "C" void kernel_launch(void* const* d_in, const int* in_sizes, int n_in,
                              void* d_out, int out_size) {
    const float* A = (const float*)d_in[0];
    const float* R = (const float*)d_in[1];
    const float* r = (const float*)d_in[2];
    const float* m = (const float*)d_in[3];
    const float* s = (const float*)d_in[4];
    const float* h = (const float*)d_in[5];
    const float* a = (const float*)d_in[6];
    const float* b = (const float*)d_in[7];
    const float* w = (const float*)d_in[8];
    float* out = (float*)d_out;

    mega_kernel<<<GRID, NTHR>>>(A, R, r, m, s, h, a, b, w, out);
}

// round 12
// speedup vs baseline: 1.3858x; 1.3858x over previous
#include <cuda_runtime.h>
#include <math.h>

#define NK 10
#define NIMG 8    // 0..2 = A channels, 3..7 = packed kernel pairs

// ---------------- scratch (static device globals; no allocation) ----------------
__device__ __align__(16) float2 g_cA[NIMG * 65536];
__device__ __align__(16) float2 g_cB[NIMG * 65536];
__device__ float2 g_tw[128];            // tw[Ns+k] = exp(-i*pi*k/(2*Ns)), Ns in {1,4,16,64}
__device__ float  g_Asum[256][256];
__device__ double g_part[NK][256];
__device__ double g_ksum[NK];
__device__ __align__(16) float g_mu[256*256*6];

__constant__ int c_grp[NK]   = {0,0,0,1,1,1,2,2,2,0};
__constant__ int c_pairA[5]  = {0,0,1,2,2};   // C0[2j]
__constant__ int c_pairB[5]  = {0,1,1,2,0};   // C0[2j+1]

__device__ __forceinline__ float2 cadd(float2 a, float2 b){ return make_float2(a.x+b.x, a.y+b.y); }
__device__ __forceinline__ float2 csub(float2 a, float2 b){ return make_float2(a.x-b.x, a.y-b.y); }
__device__ __forceinline__ float2 cmul(float2 a, float2 b){
    return make_float2(a.x*b.x - a.y*b.y, a.x*b.y + a.y*b.x);
}

// ---------------- kernel-profile value ----------------
__device__ __forceinline__ float kval(float D, float invS,
                                      const float* a, const float* b, const float* w, int k) {
    float Dk = D * invS;
    float val = 0.0f;
    if (Dk < 2.9f) {   // reference's fp32 tanh saturates -> sig exactly 0 past ~2.81
        float ker = 0.0f;
        #pragma unroll
        for (int t = 0; t < 3; t++) {
            float d = Dk - a[k*3+t];
            ker += b[k*3+t] * __expf(-__fdividef(d*d, w[k*3+t]));
        }
        // 0.5*(tanh(-(Dk-1)*5)+1) == 1/(1+exp((Dk-1)*10))
        float sig = __fdividef(1.0f, 1.0f + __expf((Dk - 1.0f) * 10.0f));
        val = sig * ker;
    }
    return val;
}

// ---------------- 1. init: prep rows (blk<256) + quadrant kbuild (blk>=256) ------
__global__ void __launch_bounds__(256) init_kernel(
    const float* __restrict__ A,
    const float* __restrict__ R,
    const float* __restrict__ r,
    const float* __restrict__ a,
    const float* __restrict__ b,
    const float* __restrict__ w)
{
    __shared__ double sd[256];
    int blk = blockIdx.x, tid = threadIdx.x;

    if (blk < 256) {                 // ---- prep ----
        int x = blk, y = tid;
        float a0 = A[(x*256+y)*3+0];
        float a1 = A[(x*256+y)*3+1];
        float a2 = A[(x*256+y)*3+2];
        g_Asum[x][y] = a0 + a1 + a2;
        int idx = x*256 + y;
        g_cA[0*65536 + idx] = make_float2(a0, 0.f);
        g_cA[1*65536 + idx] = make_float2(a1, 0.f);
        g_cA[2*65536 + idx] = make_float2(a2, 0.f);
        if (x == 0 && y < 128) {
            if (y == 0) {
                g_tw[0] = make_float2(1.f, 0.f);
            } else {
                int pp = 31 - __clz(y);
                int Ns = 1 << pp;
                int kk = y - Ns;
                double ang = -M_PI * (double)kk / (2.0 * (double)Ns);
                g_tw[y] = make_float2((float)cos(ang), (float)sin(ang));
            }
        }
        return;
    }

    // ---- kbuild: one quadrant, mirrored 4x ----
    int job = blk - 256;             // 0..644
    int p = job / 129;               // kernel pair 0..4
    int i = job - p*129;             // |dx| = 0..128
    int j = tid;                     // |dy| (active j<=128)
    int k0 = 2*p, k1 = 2*p + 1;
    int im = (256 - i) & 255;
    int jm = (256 - j) & 255;

    float v0 = 0.f, v1 = 0.f;
    if (j <= 128) {
        float D = sqrtf((float)(i*i + j*j));
        float Rv = R[0] + 15.0f;
        v0 = kval(D, __fdividef(1.0f, Rv * r[k0]), a, b, w, k0);
        v1 = kval(D, __fdividef(1.0f, Rv * r[k1]), a, b, w, k1);
        float2 kp = make_float2(v0, v1);
        float2* base = g_cA + (3+p)*65536;
        base[i*256 + j] = kp;
        if (jm != j) base[i*256 + jm] = kp;
        if (im != i) {
            base[im*256 + j] = kp;
            if (jm != j) base[im*256 + jm] = kp;
        }
    }

    double wgt = (j >= 1 && j <= 127) ? 2.0 : ((j <= 128) ? 1.0 : 0.0);
    sd[tid] = wgt * (double)v0;
    __syncthreads();
    for (int st = 128; st > 0; st >>= 1) {
        if (tid < st) sd[tid] += sd[tid + st];
        __syncthreads();
    }
    if (tid == 0) {
        g_part[k0][i] = sd[0];
        if (im != i) g_part[k0][im] = sd[0];
    }
    __syncthreads();
    sd[tid] = wgt * (double)v1;
    __syncthreads();
    for (int st = 128; st > 0; st >>= 1) {
        if (tid < st) sd[tid] += sd[tid + st];
        __syncthreads();
    }
    if (tid == 0) {
        g_part[k1][i] = sd[0];
        if (im != i) g_part[k1][im] = sd[0];
    }
}

// ---------------- 2. radix-4 Stockham 256-pt FFT pass, 8 rows/block --------------
// MODE 0: g_cA -> g_cB (forward pass 1; extra block 256 computes ksum)
// MODE 1: g_cB -> g_cA (forward pass 2 / inverse pass 2)
// MODE 2: fused multiply+conj: read spectra from g_cA, FFT, -> g_cB (inverse pass 1)
// Every pass writes transposed; two passes restore natural order.
template <int MODE>
__global__ void __launch_bounds__(512) fft8_pass() {
    __shared__ float2 sb[2][8][258];   // +2 pad: bank-conflict-reduced transposed store
    __shared__ double sd[256];
    int tid = threadIdx.x;
    int blk = blockIdx.x;

    if (MODE == 0 && blk >= 256) {     // ---- ksum (deterministic) ----
        for (int k = 0; k < NK; k++) {
            if (tid < 256) sd[tid] = g_part[k][tid];
            __syncthreads();
            for (int st = 128; st > 0; st >>= 1) {
                if (tid < st) sd[tid] += sd[tid + st];
                __syncthreads();
            }
            if (tid == 0) g_ksum[k] = sd[0];
            __syncthreads();
        }
        return;
    }

    int tx = tid & 63;
    int ty = tid >> 6;                 // 0..7
    int img = blk >> 5;
    int rb  = (blk & 31) * 8;
    int row = rb + ty;
    float2* B0 = sb[0][ty];

    if (MODE == 2) {
        // conj(Q), Q = fK_a*fA_a + i*fK_b*fA_b ; fK_a = Re(Kpack), fK_b = Im(Kpack)
        const float2* Kp = g_cA + (3+img)*65536 + row*256;
        const float2* Fa = g_cA + c_pairA[img]*65536 + row*256;
        const float2* Fb = g_cA + c_pairB[img]*65536 + row*256;
        #pragma unroll
        for (int i = 0; i < 4; i++) {
            int q = tx + i*64;
            float2 kp = Kp[q];
            float2 fa = Fa[q];
            float2 fb = Fb[q];
            B0[q] = make_float2(kp.x*fa.x - kp.y*fb.y, -(kp.x*fa.y) - kp.y*fb.x);
        }
    } else {
        const float2* src = (MODE == 0 ? g_cA : g_cB) + img*65536 + row*256;
        #pragma unroll
        for (int i = 0; i < 4; i++) B0[tx + i*64] = src[tx + i*64];
    }
    __syncthreads();

    #pragma unroll
    for (int p = 0; p < 4; p++) {
        float2* X = sb[p & 1][ty];
        float2* Y = sb[(p + 1) & 1][ty];
        int Ns = 1 << (2*p);
        int kk = tx & (Ns - 1);
        float2 av = X[tx];
        float2 bv = X[tx + 64];
        float2 cv = X[tx + 128];
        float2 dv = X[tx + 192];
        if (p > 0) {                   // stage 0 twiddles are all 1
            float2 w1 = g_tw[Ns + kk];
            float2 w2 = cmul(w1, w1);
            float2 w3 = cmul(w2, w1);
            bv = cmul(bv, w1); cv = cmul(cv, w2); dv = cmul(dv, w3);
        }
        float2 t0 = cadd(av, cv), t1 = csub(av, cv), t2 = cadd(bv, dv);
        float2 bd = csub(bv, dv);
        float2 t3 = make_float2(bd.y, -bd.x);      // -i*(b-d)
        int o = ((tx >> (2*p)) << (2*p + 2)) + kk;
        Y[o]        = cadd(t0, t2);
        Y[o + Ns]   = cadd(t1, t3);
        Y[o + 2*Ns] = csub(t0, t2);
        Y[o + 3*Ns] = csub(t1, t3);
        __syncthreads();
    }

    // cooperative transposed store from sb[0]
    float2* dst = (MODE == 1 ? g_cA : g_cB) + img*65536;
    #pragma unroll
    for (int i = 0; i < 4; i++) {
        int e = tid + i*512;
        int q = e >> 3, rr = e & 7;
        dst[q*256 + rb + rr] = sb[0][rr][q];
    }
}

// ---------------- 3. fused growth+combine+sobel+mu (16x16 tile, halo 1) ----------
__device__ __forceinline__ float padv(const float* p, int xx, int yy) {
    return (xx >= 0 && xx < 256 && yy >= 0 && yy < 256) ? p[xx*256 + yy] : 0.0f;
}

__global__ void __launch_bounds__(256) musolve_kernel(
    const float* __restrict__ A,
    const float* __restrict__ m,
    const float* __restrict__ s,
    const float* __restrict__ h)
{
    __shared__ float s_u[18*18*3];
    __shared__ float s_invk[NK], s_m[NK], s_s[NK], s_h[NK];
    int tid = threadIdx.x, bx = blockIdx.x;
    int X0 = (bx >> 4) * 16, Y0 = (bx & 15) * 16;

    if (tid < NK) {
        s_invk[tid] = (float)(1.0 / (65536.0 * g_ksum[tid]));
        s_m[tid] = m[tid]; s_s[tid] = s[tid]; s_h[tid] = h[tid];
    }
    __syncthreads();

    // growth + channel-group sums over the 18x18 halo tile (zero outside grid)
    for (int e = tid; e < 18*18; e += 256) {
        int ii = e / 18, jj = e - ii*18;
        int gx = X0 - 1 + ii, gy = Y0 - 1 + jj;
        float u0 = 0.f, u1 = 0.f, u2 = 0.f;
        if (gx >= 0 && gx < 256 && gy >= 0 && gy < 256) {
            int idx = gx*256 + gy;
            #pragma unroll
            for (int j = 0; j < 5; j++) {
                float2 z = g_cA[j*65536 + idx];
                #pragma unroll
                for (int q = 0; q < 2; q++) {
                    int k = 2*j + q;
                    float U = (q == 0 ? z.x : -z.y) * s_invk[k];
                    float gg = (U - s_m[k]) / s_s[k];
                    float gr = (__expf(-0.5f * gg * gg) * 2.0f - 1.0f) * s_h[k];
                    int grp = c_grp[k];
                    if (grp == 0) u0 += gr;
                    else if (grp == 1) u1 += gr;
                    else u2 += gr;
                }
            }
        }
        s_u[e*3+0] = u0; s_u[e*3+1] = u1; s_u[e*3+2] = u2;
    }
    __syncthreads();

    int lx = tid >> 4, ly = tid & 15;
    int x = X0 + lx, y = Y0 + ly;
    const float* As = &g_Asum[0][0];
    float nA0 = (padv(As,x-1,y-1) + 2.0f*padv(As,x-1,y) + padv(As,x-1,y+1))
              - (padv(As,x+1,y-1) + 2.0f*padv(As,x+1,y) + padv(As,x+1,y+1));
    float nA1 = (padv(As,x-1,y-1) + 2.0f*padv(As,x,y-1) + padv(As,x+1,y-1))
              - (padv(As,x-1,y+1) + 2.0f*padv(As,x,y+1) + padv(As,x+1,y+1));

    float px = (float)x + 0.5f;
    float py = (float)y + 0.5f;
    #pragma unroll
    for (int c = 0; c < 3; c++) {
        #define SU(ii,jj) s_u[(((ii))*18 + (jj))*3 + c]
        float nU0 = (SU(lx,ly)   + 2.0f*SU(lx,ly+1)   + SU(lx,ly+2))
                  - (SU(lx+2,ly) + 2.0f*SU(lx+2,ly+1) + SU(lx+2,ly+2));
        float nU1 = (SU(lx,ly)   + 2.0f*SU(lx+1,ly)   + SU(lx+2,ly))
                  - (SU(lx,ly+2) + 2.0f*SU(lx+1,ly+2) + SU(lx+2,ly+2));
        #undef SU
        float Ac = A[(x*256+y)*3 + c];
        float al = Ac * (1.0f/3.0f);
        al = al * al;
        al = fminf(al, 1.0f);
        float F0 = nU0 * (1.0f - al) - nA0 * al;
        float F1 = nU1 * (1.0f - al) - nA1 * al;
        float d0 = fminf(fmaxf(0.2f * F0, -4.35f), 4.35f);
        float d1 = fminf(fmaxf(0.2f * F1, -4.35f), 4.35f);
        float mux = fminf(fmaxf(px + d0, 0.65f), 255.35f);
        float muy = fminf(fmaxf(py + d1, 0.65f), 255.35f);
        g_mu[(x*256+y)*6 + c*2 + 0] = mux;
        g_mu[(x*256+y)*6 + c*2 + 1] = muy;
    }
}

// ---------------- 4. reintegration tracking (smem-tiled gather) ----------------
__global__ void __launch_bounds__(256) gather_kernel(const float* __restrict__ A,
                                                     float* __restrict__ out) {
    __shared__ float s_mu[26*26*6];
    __shared__ float s_a[26*26*3];
    int tid = threadIdx.x;
    int tx = tid & 15;
    int ty = tid >> 4;
    int X0 = blockIdx.x * 16, Y0 = blockIdx.y * 16;

    for (int idx = tid; idx < 26*26; idx += 256) {
        int ii = idx / 26, jj = idx - ii*26;
        int gi = (X0 - 5 + ii) & 255;
        int gj = (Y0 - 5 + jj) & 255;
        const float2* mu = (const float2*)(g_mu + (gi*256 + gj)*6);
        float2* d = (float2*)(s_mu + idx*6);
        d[0] = mu[0]; d[1] = mu[1]; d[2] = mu[2];
        s_a[idx*3+0] = A[(gi*256+gj)*3+0];
        s_a[idx*3+1] = A[(gi*256+gj)*3+1];
        s_a[idx*3+2] = A[(gi*256+gj)*3+2];
    }
    __syncthreads();

    int x = X0 + ty, y = Y0 + tx;
    float px = (float)x + 0.5f;
    float py = (float)y + 0.5f;
    float acc0 = 0.0f, acc1 = 0.0f, acc2 = 0.0f;
    const float inv = 1.0f / 1.69f;   // 1/(4*sigma^2)

    #pragma unroll
    for (int dx = -5; dx <= 5; ++dx) {
        int si = ty + 5 - dx;
        #pragma unroll
        for (int dy = -5; dy <= 5; ++dy) {
            int sj = tx + 5 - dy;
            int base = si*26 + sj;
            const float* mu = s_mu + base*6;
            const float* av = s_a + base*3;
            #pragma unroll
            for (int c = 0; c < 3; c++) {
                float ax = 1.15f - fabsf(px - mu[2*c + 0]);
                float ay = 1.15f - fabsf(py - mu[2*c + 1]);
                ax = fminf(fmaxf(ax, 0.0f), 1.0f);
                ay = fminf(fmaxf(ay, 0.0f), 1.0f);
                float area = ax * ay * inv;
                if (c == 0) acc0 = fmaf(av[0], area, acc0);
                else if (c == 1) acc1 = fmaf(av[1], area, acc1);
                else acc2 = fmaf(av[2], area, acc2);
            }
        }
    }
    out[(x*256+y)*3 + 0] = acc0;
    out[(x*256+y)*3 + 1] = acc1;
    out[(x*256+y)*3 + 2] = acc2;
}

// ---------------- launch ----------------
extern "C" void kernel_launch(void* const* d_in, const int* in_sizes, int n_in,
                              void* d_out, int out_size) {
    const float* A = (const float*)d_in[0];
    const float* R = (const float*)d_in[1];
    const float* r = (const float*)d_in[2];
    const float* m = (const float*)d_in[3];
    const float* s = (const float*)d_in[4];
    const float* h = (const float*)d_in[5];
    const float* a = (const float*)d_in[6];
    const float* b = (const float*)d_in[7];
    const float* w = (const float*)d_in[8];
    float* out = (float*)d_out;

    init_kernel<<<256 + 5*129, 256>>>(A, R, r, a, b, w);
    // forward 2D FFT of 8 images (two transposing passes); block 256 of pass 1 = ksum
    fft8_pass<0><<<257, 512>>>();
    fft8_pass<1><<<256, 512>>>();
    // inverse of 5 packed products (mult+conj fused into pass 1)
    fft8_pass<2><<<160, 512>>>();
    fft8_pass<1><<<160, 512>>>();
    musolve_kernel<<<256, 256>>>(A, m, s, h);
    gather_kernel<<<dim3(16, 16), 256>>>(A, out);
}

// round 13
// speedup vs baseline: 1.5820x; 1.1416x over previous
#include <cuda_runtime.h>
#include <math.h>

#define NK 10
#define NIMG 8    // 0..2 = A channels, 3..7 = packed kernel pairs

// ---------------- scratch (static device globals; no allocation) ----------------
__device__ __align__(16) float2 g_cA[NIMG * 65536];
__device__ __align__(16) float2 g_cB[NIMG * 65536];
__device__ __align__(16) float2 g_gr[5 * 65536];   // growth pairs (gr_2j, gr_2j+1)
__device__ float2 g_tw[128];            // tw[Ns+k] = exp(-i*pi*k/(2*Ns)), Ns in {1,4,16,64}
__device__ float  g_Asum[256][256];
__device__ double g_part[NK][256];
__device__ double g_ksum[NK];
__device__ __align__(16) float g_mu[256*256*6];

__constant__ int c_pairA[5]  = {0,0,1,2,2};   // C0[2j]
__constant__ int c_pairB[5]  = {0,1,1,2,0};   // C0[2j+1]

__device__ __forceinline__ float2 cadd(float2 a, float2 b){ return make_float2(a.x+b.x, a.y+b.y); }
__device__ __forceinline__ float2 csub(float2 a, float2 b){ return make_float2(a.x-b.x, a.y-b.y); }
__device__ __forceinline__ float2 cmul(float2 a, float2 b){
    return make_float2(a.x*b.x - a.y*b.y, a.x*b.y + a.y*b.x);
}

// ---------------- kernel-profile value ----------------
__device__ __forceinline__ float kval(float D, float invS,
                                      const float* a, const float* b, const float* w, int k) {
    float Dk = D * invS;
    float val = 0.0f;
    if (Dk < 2.9f) {   // reference's fp32 tanh saturates -> sig exactly 0 past ~2.81
        float ker = 0.0f;
        #pragma unroll
        for (int t = 0; t < 3; t++) {
            float d = Dk - a[k*3+t];
            ker += b[k*3+t] * __expf(-__fdividef(d*d, w[k*3+t]));
        }
        float sig = __fdividef(1.0f, 1.0f + __expf((Dk - 1.0f) * 10.0f));
        val = sig * ker;
    }
    return val;
}

// ---------------- 1. init: prep rows (blk<256) + quadrant kbuild (blk>=256) ------
__global__ void __launch_bounds__(256) init_kernel(
    const float* __restrict__ A,
    const float* __restrict__ R,
    const float* __restrict__ r,
    const float* __restrict__ a,
    const float* __restrict__ b,
    const float* __restrict__ w)
{
    __shared__ double sd[256];
    int blk = blockIdx.x, tid = threadIdx.x;

    if (blk < 256) {                 // ---- prep ----
        int x = blk, y = tid;
        float a0 = A[(x*256+y)*3+0];
        float a1 = A[(x*256+y)*3+1];
        float a2 = A[(x*256+y)*3+2];
        g_Asum[x][y] = a0 + a1 + a2;
        int idx = x*256 + y;
        g_cA[0*65536 + idx] = make_float2(a0, 0.f);
        g_cA[1*65536 + idx] = make_float2(a1, 0.f);
        g_cA[2*65536 + idx] = make_float2(a2, 0.f);
        if (x == 0 && y < 128) {
            if (y == 0) {
                g_tw[0] = make_float2(1.f, 0.f);
            } else {
                int pp = 31 - __clz(y);
                int Ns = 1 << pp;
                int kk = y - Ns;
                double ang = -M_PI * (double)kk / (2.0 * (double)Ns);
                g_tw[y] = make_float2((float)cos(ang), (float)sin(ang));
            }
        }
        return;
    }

    // ---- kbuild: one quadrant, mirrored 4x ----
    int job = blk - 256;             // 0..644
    int p = job / 129;               // kernel pair 0..4
    int i = job - p*129;             // |dx| = 0..128
    int j = tid;                     // |dy| (active j<=128)
    int k0 = 2*p, k1 = 2*p + 1;
    int im = (256 - i) & 255;
    int jm = (256 - j) & 255;

    float v0 = 0.f, v1 = 0.f;
    if (j <= 128) {
        float D = sqrtf((float)(i*i + j*j));
        float Rv = R[0] + 15.0f;
        v0 = kval(D, __fdividef(1.0f, Rv * r[k0]), a, b, w, k0);
        v1 = kval(D, __fdividef(1.0f, Rv * r[k1]), a, b, w, k1);
        float2 kp = make_float2(v0, v1);
        float2* base = g_cA + (3+p)*65536;
        base[i*256 + j] = kp;
        if (jm != j) base[i*256 + jm] = kp;
        if (im != i) {
            base[im*256 + j] = kp;
            if (jm != j) base[im*256 + jm] = kp;
        }
    }

    double wgt = (j >= 1 && j <= 127) ? 2.0 : ((j <= 128) ? 1.0 : 0.0);
    sd[tid] = wgt * (double)v0;
    __syncthreads();
    for (int st = 128; st > 0; st >>= 1) {
        if (tid < st) sd[tid] += sd[tid + st];
        __syncthreads();
    }
    if (tid == 0) {
        g_part[k0][i] = sd[0];
        if (im != i) g_part[k0][im] = sd[0];
    }
    __syncthreads();
    sd[tid] = wgt * (double)v1;
    __syncthreads();
    for (int st = 128; st > 0; st >>= 1) {
        if (tid < st) sd[tid] += sd[tid + st];
        __syncthreads();
    }
    if (tid == 0) {
        g_part[k1][i] = sd[0];
        if (im != i) g_part[k1][im] = sd[0];
    }
}

// ---------------- 2. radix-4 Stockham 256-pt FFT pass, 2 rows/block --------------
// MODE 0: g_cA -> g_cB (forward pass 1; extra block (>=8*128) computes ksum)
// MODE 1: g_cB -> g_cA (forward pass 2)
// MODE 2: fused multiply+conj: read spectra from g_cA, FFT, -> g_cB (inverse pass 1)
// MODE 3: inverse pass 2 + fused growth: g_cB -> g_gr
// Every pass writes transposed; two passes restore natural order.
template <int MODE>
__global__ void __launch_bounds__(128) fft2_pass(
    const float* __restrict__ m,
    const float* __restrict__ s,
    const float* __restrict__ h)
{
    __shared__ float2 sb[2][2][258];
    __shared__ double sd[128];
    int tid = threadIdx.x;
    int blk = blockIdx.x;

    if (MODE == 0 && blk >= NIMG*128) {   // ---- ksum (deterministic) ----
        for (int k = 0; k < NK; k++) {
            sd[tid] = g_part[k][tid] + g_part[k][tid + 128];
            __syncthreads();
            for (int st = 64; st > 0; st >>= 1) {
                if (tid < st) sd[tid] += sd[tid + st];
                __syncthreads();
            }
            if (tid == 0) g_ksum[k] = sd[0];
            __syncthreads();
        }
        return;
    }

    int tx = tid & 63;
    int ty = tid >> 6;                 // 0..1
    int img = blk >> 7;
    int rb  = (blk & 127) * 2;
    int row = rb + ty;
    float2* B0 = sb[0][ty];

    if (MODE == 2) {
        // conj(Q), Q = fK_a*fA_a + i*fK_b*fA_b ; fK_a = Re(Kpack), fK_b = Im(Kpack)
        const float2* Kp = g_cA + (3+img)*65536 + row*256;
        const float2* Fa = g_cA + c_pairA[img]*65536 + row*256;
        const float2* Fb = g_cA + c_pairB[img]*65536 + row*256;
        #pragma unroll
        for (int i = 0; i < 4; i++) {
            int q = tx + i*64;
            float2 kp = Kp[q];
            float2 fa = Fa[q];
            float2 fb = Fb[q];
            B0[q] = make_float2(kp.x*fa.x - kp.y*fb.y, -(kp.x*fa.y) - kp.y*fb.x);
        }
    } else {
        const float2* src = (MODE == 0 ? g_cA : g_cB) + img*65536 + row*256;
        #pragma unroll
        for (int i = 0; i < 4; i++) B0[tx + i*64] = src[tx + i*64];
    }
    __syncthreads();

    #pragma unroll
    for (int p = 0; p < 4; p++) {
        float2* X = sb[p & 1][ty];
        float2* Y = sb[(p + 1) & 1][ty];
        int Ns = 1 << (2*p);
        int kk = tx & (Ns - 1);
        float2 av = X[tx];
        float2 bv = X[tx + 64];
        float2 cv = X[tx + 128];
        float2 dv = X[tx + 192];
        if (p > 0) {                   // stage 0 twiddles are all 1
            float2 w1 = g_tw[Ns + kk];
            float2 w2 = cmul(w1, w1);
            float2 w3 = cmul(w2, w1);
            bv = cmul(bv, w1); cv = cmul(cv, w2); dv = cmul(dv, w3);
        }
        float2 t0 = cadd(av, cv), t1 = csub(av, cv), t2 = cadd(bv, dv);
        float2 bd = csub(bv, dv);
        float2 t3 = make_float2(bd.y, -bd.x);      // -i*(b-d)
        int o = ((tx >> (2*p)) << (2*p + 2)) + kk;
        Y[o]        = cadd(t0, t2);
        Y[o + Ns]   = cadd(t1, t3);
        Y[o + 2*Ns] = csub(t0, t2);
        Y[o + 3*Ns] = csub(t1, t3);
        __syncthreads();
    }

    if (MODE == 3) {
        // fused growth: z = (U_2j, -U_2j+1) * 65536 * ksum  ->  store gr pair
        int k0 = 2*img, k1 = k0 + 1;
        float invk0 = (float)(1.0 / (65536.0 * g_ksum[k0]));
        float invk1 = (float)(1.0 / (65536.0 * g_ksum[k1]));
        float m0 = m[k0], m1 = m[k1];
        float is0 = __fdividef(1.0f, s[k0]), is1 = __fdividef(1.0f, s[k1]);
        float h0 = h[k0], h1 = h[k1];
        float2* dst = g_gr + img*65536;
        #pragma unroll
        for (int i = 0; i < 4; i++) {
            int e = tid + i*128;
            int q = e >> 1, rr = e & 1;
            float2 z = sb[0][rr][q];
            float U0 = z.x * invk0;
            float U1 = -z.y * invk1;
            float gg0 = (U0 - m0) * is0;
            float gg1 = (U1 - m1) * is1;
            float g0 = (__expf(-0.5f * gg0 * gg0) * 2.0f - 1.0f) * h0;
            float g1 = (__expf(-0.5f * gg1 * gg1) * 2.0f - 1.0f) * h1;
            dst[q*256 + rb + rr] = make_float2(g0, g1);
        }
    } else {
        float2* dst = (MODE == 1 ? g_cA : g_cB) + img*65536;
        #pragma unroll
        for (int i = 0; i < 4; i++) {
            int e = tid + i*128;
            int q = e >> 1, rr = e & 1;
            dst[q*256 + rb + rr] = sb[0][rr][q];
        }
    }
}

// ---------------- 3. fused combine+sobel+mu (16x16 tile, halo 1) ----------------
__device__ __forceinline__ float padv(const float* p, int xx, int yy) {
    return (xx >= 0 && xx < 256 && yy >= 0 && yy < 256) ? p[xx*256 + yy] : 0.0f;
}

__global__ void __launch_bounds__(256) musolve_kernel(const float* __restrict__ A)
{
    __shared__ float s_u[18*18*3];
    int tid = threadIdx.x, bx = blockIdx.x;
    int X0 = (bx >> 4) * 16, Y0 = (bx & 15) * 16;

    // channel-group sums of precomputed growth over the 18x18 halo tile
    for (int e = tid; e < 18*18; e += 256) {
        int ii = e / 18, jj = e - ii*18;
        int gx = X0 - 1 + ii, gy = Y0 - 1 + jj;
        float u0 = 0.f, u1 = 0.f, u2 = 0.f;
        if (gx >= 0 && gx < 256 && gy >= 0 && gy < 256) {
            int idx = gx*256 + gy;
            float2 z0 = g_gr[0*65536 + idx];   // gr0(grp0), gr1(grp0)
            float2 z1 = g_gr[1*65536 + idx];   // gr2(grp0), gr3(grp1)
            float2 z2 = g_gr[2*65536 + idx];   // gr4(grp1), gr5(grp1)
            float2 z3 = g_gr[3*65536 + idx];   // gr6(grp2), gr7(grp2)
            float2 z4 = g_gr[4*65536 + idx];   // gr8(grp2), gr9(grp0)
            u0 = z0.x + z0.y + z1.x + z4.y;
            u1 = z1.y + z2.x + z2.y;
            u2 = z3.x + z3.y + z4.x;
        }
        s_u[e*3+0] = u0; s_u[e*3+1] = u1; s_u[e*3+2] = u2;
    }
    __syncthreads();

    int lx = tid >> 4, ly = tid & 15;
    int x = X0 + lx, y = Y0 + ly;
    const float* As = &g_Asum[0][0];
    float nA0 = (padv(As,x-1,y-1) + 2.0f*padv(As,x-1,y) + padv(As,x-1,y+1))
              - (padv(As,x+1,y-1) + 2.0f*padv(As,x+1,y) + padv(As,x+1,y+1));
    float nA1 = (padv(As,x-1,y-1) + 2.0f*padv(As,x,y-1) + padv(As,x+1,y-1))
              - (padv(As,x-1,y+1) + 2.0f*padv(As,x,y+1) + padv(As,x+1,y+1));

    float px = (float)x + 0.5f;
    float py = (float)y + 0.5f;
    #pragma unroll
    for (int c = 0; c < 3; c++) {
        #define SU(ii,jj) s_u[(((ii))*18 + (jj))*3 + c]
        float nU0 = (SU(lx,ly)   + 2.0f*SU(lx,ly+1)   + SU(lx,ly+2))
                  - (SU(lx+2,ly) + 2.0f*SU(lx+2,ly+1) + SU(lx+2,ly+2));
        float nU1 = (SU(lx,ly)   + 2.0f*SU(lx+1,ly)   + SU(lx+2,ly))
                  - (SU(lx,ly+2) + 2.0f*SU(lx+1,ly+2) + SU(lx+2,ly+2));
        #undef SU
        float Ac = A[(x*256+y)*3 + c];
        float al = Ac * (1.0f/3.0f);
        al = al * al;
        al = fminf(al, 1.0f);
        float F0 = nU0 * (1.0f - al) - nA0 * al;
        float F1 = nU1 * (1.0f - al) - nA1 * al;
        float d0 = fminf(fmaxf(0.2f * F0, -4.35f), 4.35f);
        float d1 = fminf(fmaxf(0.2f * F1, -4.35f), 4.35f);
        float mux = fminf(fmaxf(px + d0, 0.65f), 255.35f);
        float muy = fminf(fmaxf(py + d1, 0.65f), 255.35f);
        g_mu[(x*256+y)*6 + c*2 + 0] = mux;
        g_mu[(x*256+y)*6 + c*2 + 1] = muy;
    }
}

// ---------------- 4. reintegration tracking (smem-tiled gather) ----------------
__global__ void __launch_bounds__(256) gather_kernel(const float* __restrict__ A,
                                                     float* __restrict__ out) {
    __shared__ float s_mu[26*26*6];
    __shared__ float s_a[26*26*3];
    int tid = threadIdx.x;
    int tx = tid & 15;
    int ty = tid >> 4;
    int X0 = blockIdx.x * 16, Y0 = blockIdx.y * 16;

    for (int idx = tid; idx < 26*26; idx += 256) {
        int ii = idx / 26, jj = idx - ii*26;
        int gi = (X0 - 5 + ii) & 255;
        int gj = (Y0 - 5 + jj) & 255;
        const float2* mu = (const float2*)(g_mu + (gi*256 + gj)*6);
        float2* d = (float2*)(s_mu + idx*6);
        d[0] = mu[0]; d[1] = mu[1]; d[2] = mu[2];
        s_a[idx*3+0] = A[(gi*256+gj)*3+0];
        s_a[idx*3+1] = A[(gi*256+gj)*3+1];
        s_a[idx*3+2] = A[(gi*256+gj)*3+2];
    }
    __syncthreads();

    int x = X0 + ty, y = Y0 + tx;
    float px = (float)x + 0.5f;
    float py = (float)y + 0.5f;
    float acc0 = 0.0f, acc1 = 0.0f, acc2 = 0.0f;
    const float inv = 1.0f / 1.69f;   // 1/(4*sigma^2)

    #pragma unroll
    for (int dx = -5; dx <= 5; ++dx) {
        int si = ty + 5 - dx;
        #pragma unroll
        for (int dy = -5; dy <= 5; ++dy) {
            int sj = tx + 5 - dy;
            int base = si*26 + sj;
            const float* mu = s_mu + base*6;
            const float* av = s_a + base*3;
            #pragma unroll
            for (int c = 0; c < 3; c++) {
                float ax = 1.15f - fabsf(px - mu[2*c + 0]);
                float ay = 1.15f - fabsf(py - mu[2*c + 1]);
                ax = fminf(fmaxf(ax, 0.0f), 1.0f);
                ay = fminf(fmaxf(ay, 0.0f), 1.0f);
                float area = ax * ay * inv;
                if (c == 0) acc0 = fmaf(av[0], area, acc0);
                else if (c == 1) acc1 = fmaf(av[1], area, acc1);
                else acc2 = fmaf(av[2], area, acc2);
            }
        }
    }
    out[(x*256+y)*3 + 0] = acc0;
    out[(x*256+y)*3 + 1] = acc1;
    out[(x*256+y)*3 + 2] = acc2;
}

// ---------------- launch ----------------
extern "C" void kernel_launch(void* const* d_in, const int* in_sizes, int n_in,
                              void* d_out, int out_size) {
    const float* A = (const float*)d_in[0];
    const float* R = (const float*)d_in[1];
    const float* r = (const float*)d_in[2];
    const float* m = (const float*)d_in[3];
    const float* s = (const float*)d_in[4];
    const float* h = (const float*)d_in[5];
    const float* a = (const float*)d_in[6];
    const float* b = (const float*)d_in[7];
    const float* w = (const float*)d_in[8];
    float* out = (float*)d_out;

    init_kernel<<<256 + 5*129, 256>>>(A, R, r, a, b, w);
    // forward 2D FFT of 8 images (two transposing passes); extra block of pass 1 = ksum
    fft2_pass<0><<<NIMG*128 + 1, 128>>>(m, s, h);
    fft2_pass<1><<<NIMG*128, 128>>>(m, s, h);
    // inverse of 5 packed products (mult+conj fused into pass 1, growth into pass 2)
    fft2_pass<2><<<5*128, 128>>>(m, s, h);
    fft2_pass<3><<<5*128, 128>>>(m, s, h);
    musolve_kernel<<<256, 256>>>(A);
    gather_kernel<<<dim3(16, 16), 256>>>(A, out);
}